// round 2
// baseline (speedup 1.0000x reference)
#include <cuda_runtime.h>

#define GN 512
#define GBATCH 16
#define R_OUT 8                 // output rows per block
#define XR (R_OUT + 4)          // x rows staged (2-halo each side) = 12
#define PR (R_OUT + 2)          // intermediate / b rows = 10
#define MAXITER 20
#define SMEM_BYTES ((XR + PR + PR) * GN * 4)   // 64 KB

// Scratch ping-pong buffer (16 MB) — __device__ global, no runtime allocation.
__device__ float g_scratch[GBATCH * GN * GN];

// Two fused Jacobi sweeps per launch.
// src_sel: 0 = u, 1 = g_scratch, 2 = out ; dst_sel: 0 = out, 1 = g_scratch
__global__ void __launch_bounds__(512) jacobi2(
    const float* __restrict__ u,
    const float* __restrict__ b,
    float* __restrict__ out,
    int src_sel, int dst_sel)
{
    extern __shared__ float sm[];
    float* sx = sm;                     // XR rows of x
    float* sb = sm + XR * GN;           // PR rows of b
    float* sp = sm + (XR + PR) * GN;    // PR rows of x'

    const float* x = (src_sel == 0) ? u
                   : (src_sel == 1) ? (const float*)g_scratch
                                    : (const float*)out;
    float* o = dst_sel ? g_scratch : out;

    const int tid = threadIdx.x;                  // 0..511
    const int r0  = blockIdx.x * R_OUT;           // first output row
    const size_t base = (size_t)blockIdx.y * (GN * GN);
    const float* xb = x + base;
    const float* bb = b + base;
    float*       ob = o + base;

    // ---- stage x rows [r0-2, r0+R_OUT+1] and b rows [r0-1, r0+R_OUT] ----
    #pragma unroll
    for (int f = tid; f < XR * (GN / 4); f += 512) {
        const int row = f >> 7, c4 = (f & 127) << 2;
        const int g = r0 - 2 + row;
        float4 v = make_float4(0.f, 0.f, 0.f, 0.f);
        if (g >= 0 && g < GN) v = *reinterpret_cast<const float4*>(xb + g * GN + c4);
        *reinterpret_cast<float4*>(sx + row * GN + c4) = v;
    }
    for (int f = tid; f < PR * (GN / 4); f += 512) {
        const int row = f >> 7, c4 = (f & 127) << 2;
        const int g = r0 - 1 + row;
        float4 v = make_float4(0.f, 0.f, 0.f, 0.f);
        if (g >= 0 && g < GN) v = *reinterpret_cast<const float4*>(bb + g * GN + c4);
        *reinterpret_cast<float4*>(sb + row * GN + c4) = v;
    }
    __syncthreads();

    // ---- step 1: x' on rows [r0-1, r0+R_OUT] (PR rows) ----
    for (int f = tid; f < PR * (GN / 4); f += 512) {
        const int k = f >> 7, j = (f & 127) << 2;
        const int g = r0 - 1 + k;
        float4 res = make_float4(0.f, 0.f, 0.f, 0.f);
        if (g >= 0 && g < GN) {
            const float* cr = sx + (k + 1) * GN;
            const float4 c  = *reinterpret_cast<const float4*>(cr + j);
            const float4 up = *reinterpret_cast<const float4*>(sx + k * GN + j);
            const float4 dn = *reinterpret_cast<const float4*>(sx + (k + 2) * GN + j);
            const float4 bv = *reinterpret_cast<const float4*>(sb + k * GN + j);
            const float l = (j > 0)      ? cr[j - 1] : 0.f;
            const float r = (j + 4 < GN) ? cr[j + 4] : 0.f;
            res.x = 0.25f * (bv.x + l   + c.y + up.x + dn.x);
            res.y = 0.25f * (bv.y + c.x + c.z + up.y + dn.y);
            res.z = 0.25f * (bv.z + c.y + c.w + up.z + dn.z);
            res.w = 0.25f * (bv.w + c.z + r   + up.w + dn.w);
        }
        *reinterpret_cast<float4*>(sp + k * GN + j) = res;
    }
    __syncthreads();

    // ---- step 2: x'' on rows [r0, r0+R_OUT-1] -> global ----
    #pragma unroll
    for (int f = tid; f < R_OUT * (GN / 4); f += 512) {
        const int k = f >> 7, j = (f & 127) << 2;
        const int g = r0 + k;
        const float* cr = sp + (k + 1) * GN;
        const float4 c  = *reinterpret_cast<const float4*>(cr + j);
        const float4 up = *reinterpret_cast<const float4*>(sp + k * GN + j);
        const float4 dn = *reinterpret_cast<const float4*>(sp + (k + 2) * GN + j);
        const float4 bv = *reinterpret_cast<const float4*>(sb + (k + 1) * GN + j);
        const float l = (j > 0)      ? cr[j - 1] : 0.f;
        const float r = (j + 4 < GN) ? cr[j + 4] : 0.f;
        float4 res;
        res.x = 0.25f * (bv.x + l   + c.y + up.x + dn.x);
        res.y = 0.25f * (bv.y + c.x + c.z + up.y + dn.y);
        res.z = 0.25f * (bv.z + c.y + c.w + up.z + dn.z);
        res.w = 0.25f * (bv.w + c.z + r   + up.w + dn.w);
        *reinterpret_cast<float4*>(ob + g * GN + j) = res;
    }
}

extern "C" void kernel_launch(void* const* d_in, const int* in_sizes, int n_in,
                              void* d_out, int out_size)
{
    const float* u = (const float*)d_in[0];
    const float* b = (const float*)d_in[1];
    float* out = (float*)d_out;

    cudaFuncSetAttribute(jacobi2, cudaFuncAttributeMaxDynamicSharedMemorySize, SMEM_BYTES);

    dim3 block(512);
    dim3 grid(GN / R_OUT, GBATCH);   // 64 row-tiles x 16 batches = 1024 blocks

    const int nfused = MAXITER / 2;  // 10 launches, 2 sweeps each
    int prev_dst = -1;
    for (int f = 0; f < nfused; ++f) {
        int dst = ((nfused - 1 - f) & 1);            // last one lands in out
        int src = (f == 0) ? 0 : (prev_dst ? 1 : 2);
        jacobi2<<<grid, block, SMEM_BYTES>>>(u, b, out, src, dst);
        prev_dst = dst;
    }
}

// round 3
// speedup vs baseline: 1.1837x; 1.1837x over previous
#include <cuda_runtime.h>

#define GN 512
#define GBATCH 16
#define R_OUT 8                 // output rows per block
#define PR (R_OUT + 2)          // intermediate x' rows = 10
#define MAXITER 20

// Scratch ping-pong buffer (16 MB) — __device__ global, no runtime allocation.
__device__ float g_scratch[GBATCH * GN * GN];

// Two fused Jacobi sweeps per launch. Step 1 reads x straight from global
// (L1 carries the 3x vertical reuse) and writes x' to smem; step 2 reads x'
// from smem + b from global (L1 hit) and writes x'' to global.
// src_sel: 0 = u, 1 = g_scratch, 2 = out ; dst_sel: 0 = out, 1 = g_scratch
__global__ void __launch_bounds__(512) jacobi2(
    const float* __restrict__ u,
    const float* __restrict__ b,
    float* __restrict__ out,
    int src_sel, int dst_sel)
{
    __shared__ float sp[PR * GN];   // 20 KB: x' rows [r0-1, r0+R_OUT]

    const float* x = (src_sel == 0) ? u
                   : (src_sel == 1) ? (const float*)g_scratch
                                    : (const float*)out;
    float* o = dst_sel ? g_scratch : out;

    const int tid = threadIdx.x;                  // 0..511
    const int r0  = blockIdx.x * R_OUT;           // first output row
    const size_t base = (size_t)blockIdx.y * (GN * GN);
    const float* xb = x + base;
    const float* bb = b + base;
    float*       ob = o + base;

    // ---- step 1: x' rows [r0-1, r0+R_OUT], global -> smem ----
    #pragma unroll
    for (int f = tid; f < PR * (GN / 4); f += 512) {
        const int k = f >> 7;             // 0..PR-1
        const int j = (f & 127) << 2;     // column (multiple of 4)
        const int g = r0 - 1 + k;         // global row
        float4 res = make_float4(0.f, 0.f, 0.f, 0.f);
        if (g >= 0 && g < GN) {
            const int idx = g * GN + j;
            const float4 c  = *reinterpret_cast<const float4*>(xb + idx);
            const float4 bv = *reinterpret_cast<const float4*>(bb + idx);
            float4 up = make_float4(0.f, 0.f, 0.f, 0.f);
            float4 dn = make_float4(0.f, 0.f, 0.f, 0.f);
            if (g > 0)      up = *reinterpret_cast<const float4*>(xb + idx - GN);
            if (g < GN - 1) dn = *reinterpret_cast<const float4*>(xb + idx + GN);
            const float l = (j > 0)      ? xb[idx - 1] : 0.f;
            const float r = (j + 4 < GN) ? xb[idx + 4] : 0.f;
            res.x = 0.25f * (bv.x + l   + c.y + up.x + dn.x);
            res.y = 0.25f * (bv.y + c.x + c.z + up.y + dn.y);
            res.z = 0.25f * (bv.z + c.y + c.w + up.z + dn.z);
            res.w = 0.25f * (bv.w + c.z + r   + up.w + dn.w);
        }
        *reinterpret_cast<float4*>(sp + k * GN + j) = res;
    }
    __syncthreads();

    // ---- step 2: x'' rows [r0, r0+R_OUT-1], smem + b(L1) -> global ----
    #pragma unroll
    for (int f = tid; f < R_OUT * (GN / 4); f += 512) {
        const int k = f >> 7;             // 0..R_OUT-1
        const int j = (f & 127) << 2;
        const int g = r0 + k;
        const float* cr = sp + (k + 1) * GN;
        const float4 c  = *reinterpret_cast<const float4*>(cr + j);
        const float4 up = *reinterpret_cast<const float4*>(sp + k * GN + j);
        const float4 dn = *reinterpret_cast<const float4*>(sp + (k + 2) * GN + j);
        const float4 bv = *reinterpret_cast<const float4*>(bb + g * GN + j);
        const float l = (j > 0)      ? cr[j - 1] : 0.f;
        const float r = (j + 4 < GN) ? cr[j + 4] : 0.f;
        float4 res;
        res.x = 0.25f * (bv.x + l   + c.y + up.x + dn.x);
        res.y = 0.25f * (bv.y + c.x + c.z + up.y + dn.y);
        res.z = 0.25f * (bv.z + c.y + c.w + up.z + dn.z);
        res.w = 0.25f * (bv.w + c.z + r   + up.w + dn.w);
        *reinterpret_cast<float4*>(ob + g * GN + j) = res;
    }
}

extern "C" void kernel_launch(void* const* d_in, const int* in_sizes, int n_in,
                              void* d_out, int out_size)
{
    const float* u = (const float*)d_in[0];
    const float* b = (const float*)d_in[1];
    float* out = (float*)d_out;

    dim3 block(512);
    dim3 grid(GN / R_OUT, GBATCH);   // 64 row-tiles x 16 batches = 1024 blocks

    const int nfused = MAXITER / 2;  // 10 launches, 2 sweeps each
    int prev_dst = -1;
    for (int f = 0; f < nfused; ++f) {
        int dst = ((nfused - 1 - f) & 1);            // last one lands in out
        int src = (f == 0) ? 0 : (prev_dst ? 1 : 2);
        jacobi2<<<grid, block>>>(u, b, out, src, dst);
        prev_dst = dst;
    }
}

// round 4
// speedup vs baseline: 1.2798x; 1.0812x over previous
#include <cuda_runtime.h>

#define GN 512
#define GBATCH 16
#define RSTRIP 16
#define MAXITER 20

// Scratch ping-pong buffer (16 MB) — __device__ global, no runtime allocation.
__device__ float g_scratch[GBATCH * GN * GN];

__device__ __forceinline__ float4 ld4(const float* p) {
    return *reinterpret_cast<const float4*>(p);
}

// One Jacobi row update from 3 x-rows in registers (up, mid, dn) + b row.
// Horizontal neighbors of `mid` via warp shuffles; warp-edge values eL/eR
// supplied by caller (global scalar loads or 0 at grid edge).
__device__ __forceinline__ float4 jrow(float4 up, float4 mid, float4 dn, float4 bv,
                                       float eL, float eR, int lane)
{
    float l = __shfl_up_sync(0xffffffffu, mid.w, 1);
    float r = __shfl_down_sync(0xffffffffu, mid.x, 1);
    if (lane == 0)  l = eL;
    if (lane == 31) r = eR;
    float4 res;
    res.x = 0.25f * (bv.x + l     + mid.y + up.x + dn.x);
    res.y = 0.25f * (bv.y + mid.x + mid.z + up.y + dn.y);
    res.z = 0.25f * (bv.z + mid.y + mid.w + up.z + dn.z);
    res.w = 0.25f * (bv.w + mid.z + r     + up.w + dn.w);
    return res;
}

// Two fused Jacobi sweeps, register-marching down a RSTRIP-row strip.
// Block = 4 warps covering the full 512-col row. x' (intermediate) lives in a
// 3-row register pipeline; warp-boundary x' scalars exchanged through a tiny
// depth-4 smem ring (one __syncthreads per row).
// src_sel: 0 = u, 1 = g_scratch, 2 = out ; dst_sel: 0 = out, 1 = g_scratch
__global__ void __launch_bounds__(128) jacobi2(
    const float* __restrict__ u,
    const float* __restrict__ b,
    float* __restrict__ out,
    int src_sel, int dst_sel)
{
    __shared__ float ebuf[4][4][2];   // [ring slot][warp][left/right edge]

    const float* x = (src_sel == 0) ? u
                   : (src_sel == 1) ? (const float*)g_scratch
                                    : (const float*)out;
    float* o = dst_sel ? g_scratch : out;

    const int lane = threadIdx.x & 31;
    const int w    = threadIdx.x >> 5;        // warp 0..3 -> cols [w*128, w*128+128)
    const int wcb  = w * 128;
    const int c    = wcb + lane * 4;
    const int r0   = blockIdx.x * RSTRIP;
    const size_t base = (size_t)blockIdx.y * (GN * GN);
    const float* xg = x + base;
    const float* bg = b + base;
    float*       og = o + base;

    const float4 Z = make_float4(0.f, 0.f, 0.f, 0.f);

    // ---- prologue: build x windows and x' pipeline (pm = x'_{r0-1}, pc = x'_{r0}) ----
    float4 xm2 = (r0 >= 2) ? ld4(xg + (r0 - 2) * GN + c) : Z;
    float4 xm1 = (r0 >= 1) ? ld4(xg + (r0 - 1) * GN + c) : Z;
    float4 xa  = ld4(xg + r0 * GN + c);            // x_{i}
    float4 xb2 = ld4(xg + (r0 + 1) * GN + c);      // x_{i+1}
    float4 bc  = ld4(bg + r0 * GN + c);            // b_{i}

    float4 pm = Z;
    if (r0 >= 1) {
        float4 bm = ld4(bg + (r0 - 1) * GN + c);
        float eL = 0.f, eR = 0.f;
        if (lane == 0  && w > 0) eL = xg[(r0 - 1) * GN + wcb - 1];
        if (lane == 31 && w < 3) eR = xg[(r0 - 1) * GN + wcb + 128];
        pm = jrow(xm2, xm1, xa, bm, eL, eR, lane);
    }
    float4 pc;
    {
        float eL = 0.f, eR = 0.f;
        if (lane == 0  && w > 0) eL = xg[r0 * GN + wcb - 1];
        if (lane == 31 && w < 3) eR = xg[r0 * GN + wcb + 128];
        pc = jrow(xm1, xa, xb2, bc, eL, eR, lane);
    }
    if (lane == 0)  ebuf[3][w][0] = pc.x;
    if (lane == 31) ebuf[3][w][1] = pc.w;
    __syncthreads();

    // ---- march: output row i = r0 + t ----
    #pragma unroll 4
    for (int t = 0; t < RSTRIP; ++t) {
        const int i   = r0 + t;
        const int ip1 = i + 1, ip2 = i + 2;

        float4 xN = (ip2 < GN) ? ld4(xg + ip2 * GN + c) : Z;
        float4 pn = Z;
        float4 bn = Z;
        if (ip1 < GN) {
            bn = ld4(bg + ip1 * GN + c);
            float eL = 0.f, eR = 0.f;
            if (lane == 0  && w > 0) eL = xg[ip1 * GN + wcb - 1];
            if (lane == 31 && w < 3) eR = xg[ip1 * GN + wcb + 128];
            pn = jrow(xa, xb2, xN, bn, eL, eR, lane);   // x'_{i+1}
        }
        if (lane == 0)  ebuf[t & 3][w][0] = pn.x;
        if (lane == 31) ebuf[t & 3][w][1] = pn.w;
        __syncthreads();

        // x''_i from x' pipeline (pm, pc, pn) + b_i
        float lP = __shfl_up_sync(0xffffffffu, pc.w, 1);
        float rP = __shfl_down_sync(0xffffffffu, pc.x, 1);
        if (lane == 0)  lP = (w > 0) ? ebuf[(t + 3) & 3][w - 1][1] : 0.f;
        if (lane == 31) rP = (w < 3) ? ebuf[(t + 3) & 3][w + 1][0] : 0.f;

        float4 res;
        res.x = 0.25f * (bc.x + lP   + pc.y + pm.x + pn.x);
        res.y = 0.25f * (bc.y + pc.x + pc.z + pm.y + pn.y);
        res.z = 0.25f * (bc.z + pc.y + pc.w + pm.z + pn.z);
        res.w = 0.25f * (bc.w + pc.z + rP   + pm.w + pn.w);
        *reinterpret_cast<float4*>(og + i * GN + c) = res;

        pm = pc; pc = pn;
        xa = xb2; xb2 = xN;
        bc = bn;
    }
}

extern "C" void kernel_launch(void* const* d_in, const int* in_sizes, int n_in,
                              void* d_out, int out_size)
{
    const float* u = (const float*)d_in[0];
    const float* b = (const float*)d_in[1];
    float* out = (float*)d_out;

    dim3 block(128);                       // 4 warps = full row width
    dim3 grid(GN / RSTRIP, GBATCH);        // 32 strips x 16 batches = 512 blocks

    const int nfused = MAXITER / 2;        // 10 launches, 2 sweeps each
    int prev_dst = -1;
    for (int f = 0; f < nfused; ++f) {
        int dst = ((nfused - 1 - f) & 1);             // last one lands in out
        int src = (f == 0) ? 0 : (prev_dst ? 1 : 2);
        jacobi2<<<grid, block>>>(u, b, out, src, dst);
        prev_dst = dst;
    }
}

// round 5
// speedup vs baseline: 2.0858x; 1.6298x over previous
#include <cuda_runtime.h>

#define GN 512
#define GBATCH 16
#define RSTRIP 8
#define MAXITER 20

// Scratch ping-pong buffer (16 MB) — __device__ global, no runtime allocation.
__device__ float g_scratch[GBATCH * GN * GN];

__device__ __forceinline__ float4 ld4(const float* p) {
    return *reinterpret_cast<const float4*>(p);
}

// One Jacobi row update from 3 x-rows in registers + b row. Horizontal
// neighbors via warp shuffles; tile-edge values eL/eR injected at lanes 0/31.
__device__ __forceinline__ float4 jrow(float4 up, float4 mid, float4 dn, float4 bv,
                                       float eL, float eR, int lane)
{
    float l = __shfl_up_sync(0xffffffffu, mid.w, 1);
    float r = __shfl_down_sync(0xffffffffu, mid.x, 1);
    if (lane == 0)  l = eL;
    if (lane == 31) r = eR;
    float4 res;
    res.x = 0.25f * (bv.x + l     + mid.y + up.x + dn.x);
    res.y = 0.25f * (bv.y + mid.x + mid.z + up.y + dn.y);
    res.z = 0.25f * (bv.z + mid.y + mid.w + up.z + dn.z);
    res.w = 0.25f * (bv.w + mid.z + r     + up.w + dn.w);
    return res;
}

// Two fused Jacobi sweeps, register-marching down an RSTRIP-row strip.
// Each warp owns a 128-col tile and is FULLY INDEPENDENT: the x' value just
// outside the tile (needed by the second sweep at lanes 0/31) is recomputed
// locally from a few predicated scalar loads. No shared memory, no barriers.
// src_sel: 0 = u, 1 = g_scratch, 2 = out ; dst_sel: 0 = out, 1 = g_scratch
__global__ void __launch_bounds__(128) jacobi2(
    const float* __restrict__ u,
    const float* __restrict__ b,
    float* __restrict__ out,
    int src_sel, int dst_sel)
{
    const float* x = (src_sel == 0) ? u
                   : (src_sel == 1) ? (const float*)g_scratch
                                    : (const float*)out;
    float* o = dst_sel ? g_scratch : out;

    const int lane = threadIdx.x & 31;
    const int w    = threadIdx.x >> 5;          // warp 0..3 -> cols [w*128, w*128+128)
    const int wcb  = w * 128;
    const int c    = wcb + lane * 4;
    const int r0   = blockIdx.x * RSTRIP;
    const size_t base = (size_t)blockIdx.y * (GN * GN);
    const float* xg = x + base;
    const float* bg = b + base;
    float*       og = o + base;

    const float4 Z = make_float4(0.f, 0.f, 0.f, 0.f);

    // Edge role: lane 0 handles the column just left of the tile, lane 31 just right.
    const bool epred = (lane == 0 && w > 0) || (lane == 31 && w < 3);
    const int  ec1   = (lane == 0) ? (wcb - 1) : (wcb + 128);   // neighbor col
    const int  ec2   = (lane == 0) ? (wcb - 2) : (wcb + 129);   // next col out

    // ---- prologue: x window rows r0-2..r0+1, b row r0, edge scalars ----
    float4 xm2 = (r0 >= 2) ? ld4(xg + (r0 - 2) * GN + c) : Z;
    float4 xm1 = (r0 >= 1) ? ld4(xg + (r0 - 1) * GN + c) : Z;
    float4 xa  = ld4(xg + r0 * GN + c);            // x_{r0}
    float4 xb2 = ld4(xg + (r0 + 1) * GN + c);      // x_{r0+1}
    float4 bc  = ld4(bg + r0 * GN + c);            // b_{r0}

    float xE1m = (epred && r0 >= 1) ? xg[(r0 - 1) * GN + ec1] : 0.f;  // x[r0-1][ec1]
    float xE1u = epred ? xg[r0 * GN + ec1]       : 0.f;               // x[r0  ][ec1]
    float xE1c = epred ? xg[(r0 + 1) * GN + ec1] : 0.f;               // x[r0+1][ec1]
    float xE2u = epred ? xg[r0 * GN + ec2]       : 0.f;
    float bEu  = epred ? bg[r0 * GN + ec1]       : 0.f;

    // x'_{r0-1} and x'_{r0} (in-tile), x' at edge col for row r0
    float4 pm = Z;
    if (r0 >= 1) {
        float4 bm = ld4(bg + (r0 - 1) * GN + c);
        pm = jrow(xm2, xm1, xa, bm, xE1m, xE1m, lane);
    }
    float4 pc = jrow(xm1, xa, xb2, bc, xE1u, xE1u, lane);
    float xIn0 = (lane == 0) ? xa.x : xa.w;
    float pEc  = epred ? 0.25f * (bEu + xE2u + xIn0 + xE1m + xE1c) : 0.f;

    // ---- march: output row i = r0 + t ----
    #pragma unroll
    for (int t = 0; t < RSTRIP; ++t) {
        const int i   = r0 + t;
        const int ip1 = i + 1, ip2 = i + 2;
        const bool v1 = (ip1 < GN);

        float4 xN = (ip2 < GN) ? ld4(xg + ip2 * GN + c) : Z;
        float4 bn = v1 ? ld4(bg + ip1 * GN + c) : Z;
        float xE1d = (epred && ip2 < GN) ? xg[ip2 * GN + ec1] : 0.f;
        float xE2c = (epred && v1) ? xg[ip1 * GN + ec2] : 0.f;
        float bEc  = (epred && v1) ? bg[ip1 * GN + ec1] : 0.f;

        // x'_{i+1}: in-tile and edge scalar
        float4 pn = Z;
        if (v1) pn = jrow(xa, xb2, xN, bn, xE1c, xE1c, lane);
        float xIn1 = (lane == 0) ? xb2.x : xb2.w;
        float pEn  = (epred && v1)
                   ? 0.25f * (bEc + xE2c + xIn1 + xE1u + xE1d) : 0.f;

        // x''_i from x' pipeline (pm, pc, pn) + b_i; edge x' = pEc
        float lP = __shfl_up_sync(0xffffffffu, pc.w, 1);
        float rP = __shfl_down_sync(0xffffffffu, pc.x, 1);
        if (lane == 0)  lP = pEc;
        if (lane == 31) rP = pEc;

        float4 res;
        res.x = 0.25f * (bc.x + lP   + pc.y + pm.x + pn.x);
        res.y = 0.25f * (bc.y + pc.x + pc.z + pm.y + pn.y);
        res.z = 0.25f * (bc.z + pc.y + pc.w + pm.z + pn.z);
        res.w = 0.25f * (bc.w + pc.z + rP   + pm.w + pn.w);
        *reinterpret_cast<float4*>(og + i * GN + c) = res;

        pm = pc; pc = pn; pEc = pEn;
        xa = xb2; xb2 = xN; bc = bn;
        xE1u = xE1c; xE1c = xE1d;
    }
}

extern "C" void kernel_launch(void* const* d_in, const int* in_sizes, int n_in,
                              void* d_out, int out_size)
{
    const float* u = (const float*)d_in[0];
    const float* b = (const float*)d_in[1];
    float* out = (float*)d_out;

    dim3 block(128);                       // 4 independent warps (4 col tiles)
    dim3 grid(GN / RSTRIP, GBATCH);        // 64 strips x 16 batches = 1024 blocks

    const int nfused = MAXITER / 2;        // 10 launches, 2 sweeps each
    int prev_dst = -1;
    for (int f = 0; f < nfused; ++f) {
        int dst = ((nfused - 1 - f) & 1);             // last one lands in out
        int src = (f == 0) ? 0 : (prev_dst ? 1 : 2);
        jacobi2<<<grid, block>>>(u, b, out, src, dst);
        prev_dst = dst;
    }
}